// round 7
// baseline (speedup 1.0000x reference)
#include <cuda_runtime.h>
#include <math.h>
#include <stdint.h>

// Problem constants (fixed shapes per reference)
#define NN    50000
#define NF    2000
#define D1    64
#define HEADS 8
#define HID   8
#define NC    30
#define NCP   32          // padded stride for h2/out2 (16B alignment)
#define MAXET 1700000     // >= E(1.6M) + NN(50k)

// ---------------- scratch (device globals; no allocation allowed) ----------
__device__ float g_h1[(size_t)NN * D1];
__device__ float g_res[(size_t)NN * D1];
__device__ float g_as1[NN * HEADS];
__device__ float g_ad1[NN * HEADS];
__device__ float g_sum1[NN * HEADS];
__device__ float g_eb1[(size_t)MAXET * HEADS];
__device__ float g_out1[(size_t)NN * D1];
__device__ float g_x1[(size_t)NN * D1];
__device__ float g_h2[(size_t)NN * NCP];
__device__ float g_as2[NN];
__device__ float g_ad2[NN];
__device__ float g_sum2[NN];
__device__ float g_eb2[MAXET];
__device__ float g_out2[(size_t)NN * NCP];

// ---------------- helpers ----------------
__device__ __forceinline__ void edge_sd(const int* __restrict__ ei, int E, int e,
                                        int& s, int& d) {
    if (e < E) { s = ei[e]; d = ei[E + e]; }
    else       { s = e - E; d = e - E; }   // self loops appended
}
__device__ __forceinline__ void red_add_v4(float* addr, float a, float b, float c, float d) {
    asm volatile("red.global.add.v4.f32 [%0], {%1,%2,%3,%4};"
                 :: "l"(addr), "f"(a), "f"(b), "f"(c), "f"(d) : "memory");
}
__device__ __forceinline__ void red_add_v2(float* addr, float a, float b) {
    asm volatile("red.global.add.v2.f32 [%0], {%1,%2};"
                 :: "l"(addr), "f"(a), "f"(b) : "memory");
}
// packed f32x2: d = a*b + d (two independent fp32 FMAs, .rn — bit-exact fp32)
__device__ __forceinline__ void ffma2(uint64_t& d, uint64_t a, uint64_t b) {
    asm("fma.rn.f32x2 %0, %1, %2, %0;" : "+l"(d) : "l"(a), "l"(b));
}
__device__ __forceinline__ void upk(uint64_t v, float& lo, float& hi) {
    asm("mov.b64 {%0,%1}, %2;" : "=f"(lo), "=f"(hi) : "l"(v));
}

// ---------------- init ----------------
__global__ void k_init_all() {
    int i = blockIdx.x * blockDim.x + threadIdx.x;
    if (i < NN * D1)    g_out1[i] = 0.f;
    if (i < NN * NCP)   g_out2[i] = 0.f;
    if (i < NN * HEADS) g_sum1[i] = 0.f;
    if (i < NN)         g_sum2[i] = 0.f;
}

// ---------------- GEMM1: h1 = x@w1 ; res = x@w_res + b_res ----------------
// M=NN, K=NF, N=128 (cols 0..63 -> h1, 64..127 -> res).
// 64x128 block tile, BK=16, 256 threads, 4x8 per-thread microtile.
// A stored DUPLICATED in shared (Ad[k][2m]=Ad[k][2m+1]=a) so packed f32x2
// FMAs need zero pack movs: inner loop = 4 LDS.128 + 16 FMA2 per k-step.
#define BM 64
#define BK 16

__global__ __launch_bounds__(256, 3) void k_gemm1(const float* __restrict__ x,
                                                  const float* __restrict__ w1,
                                                  const float* __restrict__ wres,
                                                  const float* __restrict__ bres) {
    __shared__ float Ad[2][BK][136];   // duplicated A: [buf][k][2m..2m+1], padded
    __shared__ float Bs[2][BK][128];   // [buf][k][n]

    const int tid  = threadIdx.x;
    const int wid  = tid >> 5;
    const int lane = tid & 31;
    const int wm = wid >> 2;          // 0..1  (rows 0-31 / 32-63)
    const int wn = wid & 3;           // 0..3  (n groups of 32)
    const int lm = lane & 7;          // 0..7
    const int ln = lane >> 3;         // 0..3
    const int m0 = wm * 32 + lm * 4;  // rows m0..m0+3
    const int n0 = wn * 32 + ln * 4;  // cols n0..n0+3 and n0+16..n0+19
    const int mbase = blockIdx.x * BM;

    // A loader: 64 rows x 16 k = 1024 floats; thread: r=tid>>2, kq=(tid&3)*4
    const int ar  = tid >> 2;            // 0..63
    const int akq = (tid & 3) * 4;       // 0,4,8,12
    // B loader: 16 k x 128 n = 2048 floats; thread: bk=tid>>5 (+8), bn=(tid&31)*4
    const int bk  = tid >> 3;            // 0..31 -> rows 0..15 twice? no:
    // use: bk0 = tid>>5 (0..7), bn=(tid&31)*4 ; two iterations rows bk0, bk0+8
    const int bk0 = tid >> 5;
    const int bn  = (tid & 31) * 4;
    (void)bk;

    int arow = mbase + ar; if (arow >= NN) arow = NN - 1;
    const float* bsrc = (bn < 64) ? &w1[bn] : &wres[bn - 64];

    float4 arv, br0, br1;
    arv = *(const float4*)&x[(size_t)arow * NF + akq];
    br0 = *(const float4*)&bsrc[(size_t)bk0 * 64];
    br1 = *(const float4*)&bsrc[(size_t)(bk0 + 8) * 64];

    uint64_t acc[4][4];
#pragma unroll
    for (int i = 0; i < 4; i++)
#pragma unroll
        for (int j = 0; j < 4; j++) acc[i][j] = 0ull;

    // store tile 0 (A duplicated)
    {
        float av[4] = {arv.x, arv.y, arv.z, arv.w};
#pragma unroll
        for (int i = 0; i < 4; i++)
            *(float2*)&Ad[0][akq + i][2 * ar] = make_float2(av[i], av[i]);
        *(float4*)&Bs[0][bk0][bn]     = br0;
        *(float4*)&Bs[0][bk0 + 8][bn] = br1;
    }
    __syncthreads();

    const int NT = NF / BK;  // 125
    for (int kt = 0; kt < NT; kt++) {
        const int buf = kt & 1;
        if (kt + 1 < NT) {
            const int k0 = (kt + 1) * BK;
            arv = *(const float4*)&x[(size_t)arow * NF + k0 + akq];
            br0 = *(const float4*)&bsrc[(size_t)(k0 + bk0) * 64];
            br1 = *(const float4*)&bsrc[(size_t)(k0 + bk0 + 8) * 64];
        }
#pragma unroll
        for (int kk = 0; kk < BK; kk++) {
            ulonglong2 a01 = *(const ulonglong2*)&Ad[buf][kk][2 * m0];
            ulonglong2 a23 = *(const ulonglong2*)&Ad[buf][kk][2 * m0 + 4];
            ulonglong2 bA  = *(const ulonglong2*)&Bs[buf][kk][n0];
            ulonglong2 bB  = *(const ulonglong2*)&Bs[buf][kk][n0 + 16];
            uint64_t av[4] = {a01.x, a01.y, a23.x, a23.y};
            uint64_t bp[4] = {bA.x, bA.y, bB.x, bB.y};
#pragma unroll
            for (int i = 0; i < 4; i++)
#pragma unroll
                for (int j = 0; j < 4; j++) ffma2(acc[i][j], av[i], bp[j]);
        }
        if (kt + 1 < NT) {
            const int nb = buf ^ 1;
            float av[4] = {arv.x, arv.y, arv.z, arv.w};
#pragma unroll
            for (int i = 0; i < 4; i++)
                *(float2*)&Ad[nb][akq + i][2 * ar] = make_float2(av[i], av[i]);
            *(float4*)&Bs[nb][bk0][bn]     = br0;
            *(float4*)&Bs[nb][bk0 + 8][bn] = br1;
            __syncthreads();
        }
    }

    // epilogue: acc[i][j] -> rows m0+i; j=0,1 -> cols n0..n0+3; j=2,3 -> n0+16..+19
#pragma unroll
    for (int i = 0; i < 4; i++) {
        int row = mbase + m0 + i;
        if (row >= NN) continue;
        float c0, c1, c2, c3, c4, c5, c6, c7;
        upk(acc[i][0], c0, c1); upk(acc[i][1], c2, c3);
        upk(acc[i][2], c4, c5); upk(acc[i][3], c6, c7);
        float4 vA = make_float4(c0, c1, c2, c3);
        float4 vB = make_float4(c4, c5, c6, c7);
        if (n0 < 64) {
            *(float4*)&g_h1[(size_t)row * 64 + n0]      = vA;
            *(float4*)&g_h1[(size_t)row * 64 + n0 + 16] = vB;
        } else {
            int nr = n0 - 64;
            vA.x += __ldg(&bres[nr + 0]);  vA.y += __ldg(&bres[nr + 1]);
            vA.z += __ldg(&bres[nr + 2]);  vA.w += __ldg(&bres[nr + 3]);
            vB.x += __ldg(&bres[nr + 16]); vB.y += __ldg(&bres[nr + 17]);
            vB.z += __ldg(&bres[nr + 18]); vB.w += __ldg(&bres[nr + 19]);
            *(float4*)&g_res[(size_t)row * 64 + nr]      = vA;
            *(float4*)&g_res[(size_t)row * 64 + nr + 16] = vB;
        }
    }
}

// ---------------- attention coefficients per node (layer 1) ---------------
__global__ void k_att1(const float* __restrict__ asrc, const float* __restrict__ adst) {
    int n = blockIdx.x * blockDim.x + threadIdx.x;
    if (n >= NN) return;
    const float* hr = &g_h1[(size_t)n * 64];
#pragma unroll
    for (int h = 0; h < HEADS; h++) {
        float s = 0.f, d = 0.f;
#pragma unroll
        for (int c = 0; c < HID; c++) {
            float v = hr[h * HID + c];
            s += v * __ldg(&asrc[h * HID + c]);
            d += v * __ldg(&adst[h * HID + c]);
        }
        g_as1[n * HEADS + h] = s;
        g_ad1[n * HEADS + h] = d;
    }
}

// ---------------- edge passes layer 1 (one thread per edge, 8 heads) -------
__global__ void k_esum1(const int* __restrict__ ei, int E, int Etot) {
    int e = blockIdx.x * blockDim.x + threadIdx.x;
    if (e >= Etot) return;
    int s, d; edge_sd(ei, E, e, s, d);
    float4 s0 = *(const float4*)&g_as1[s * 8];
    float4 s1 = *(const float4*)&g_as1[s * 8 + 4];
    float4 d0 = *(const float4*)&g_ad1[d * 8];
    float4 d1 = *(const float4*)&g_ad1[d * 8 + 4];
    float v[8] = {s0.x + d0.x, s0.y + d0.y, s0.z + d0.z, s0.w + d0.w,
                  s1.x + d1.x, s1.y + d1.y, s1.z + d1.z, s1.w + d1.w};
    float ev[8];
#pragma unroll
    for (int h = 0; h < 8; h++) {
        float t = (v[h] > 0.f) ? v[h] : 0.2f * v[h];
        ev[h] = __expf(t);
    }
    *(float4*)&g_eb1[(size_t)e * 8]     = make_float4(ev[0], ev[1], ev[2], ev[3]);
    *(float4*)&g_eb1[(size_t)e * 8 + 4] = make_float4(ev[4], ev[5], ev[6], ev[7]);
    red_add_v4(&g_sum1[d * 8],     ev[0], ev[1], ev[2], ev[3]);
    red_add_v4(&g_sum1[d * 8 + 4], ev[4], ev[5], ev[6], ev[7]);
}

__global__ void k_emsg1(const int* __restrict__ ei, int E, int Etot,
                        float* __restrict__ a1out) {
    int e = blockIdx.x * blockDim.x + threadIdx.x;
    if (e >= Etot) return;
    int s, d; edge_sd(ei, E, e, s, d);
    float4 e0 = *(const float4*)&g_eb1[(size_t)e * 8];
    float4 e1 = *(const float4*)&g_eb1[(size_t)e * 8 + 4];
    float4 q0 = *(const float4*)&g_sum1[d * 8];
    float4 q1 = *(const float4*)&g_sum1[d * 8 + 4];
    float alpha[8] = {e0.x / (q0.x + 1e-16f), e0.y / (q0.y + 1e-16f),
                      e0.z / (q0.z + 1e-16f), e0.w / (q0.w + 1e-16f),
                      e1.x / (q1.x + 1e-16f), e1.y / (q1.y + 1e-16f),
                      e1.z / (q1.z + 1e-16f), e1.w / (q1.w + 1e-16f)};
    *(float4*)&a1out[(size_t)e * 8]     = make_float4(alpha[0], alpha[1], alpha[2], alpha[3]);
    *(float4*)&a1out[(size_t)e * 8 + 4] = make_float4(alpha[4], alpha[5], alpha[6], alpha[7]);
    const float* hr = &g_h1[(size_t)s * 64];
    float* o = &g_out1[(size_t)d * 64];
#pragma unroll
    for (int h = 0; h < 8; h++) {
        float a = alpha[h];
        float4 h0 = *(const float4*)&hr[h * 8];
        float4 h1v = *(const float4*)&hr[h * 8 + 4];
        red_add_v4(o + h * 8,     h0.x * a, h0.y * a, h0.z * a, h0.w * a);
        red_add_v4(o + h * 8 + 4, h1v.x * a, h1v.y * a, h1v.z * a, h1v.w * a);
    }
}

// ---------------- x1 = elu(out1 + b1 + res), float4 ----------------
__global__ void k_x1(const float* __restrict__ b1) {
    int i4 = blockIdx.x * blockDim.x + threadIdx.x;
    if (i4 >= NN * D1 / 4) return;
    float4 o = *(const float4*)&g_out1[(size_t)i4 * 4];
    float4 r = *(const float4*)&g_res[(size_t)i4 * 4];
    float4 b = *(const float4*)&b1[(i4 & 15) * 4];
    float4 v;
    v.x = o.x + b.x + r.x; v.y = o.y + b.y + r.y;
    v.z = o.z + b.z + r.z; v.w = o.w + b.w + r.w;
    v.x = (v.x > 0.f) ? v.x : expm1f(v.x);
    v.y = (v.y > 0.f) ? v.y : expm1f(v.y);
    v.z = (v.z > 0.f) ? v.z : expm1f(v.z);
    v.w = (v.w > 0.f) ? v.w : expm1f(v.w);
    *(float4*)&g_x1[(size_t)i4 * 4] = v;
}

// ---------------- GEMM2 + attention coefficients (layer 2) ----------------
__global__ __launch_bounds__(128) void k_gemm2(const float* __restrict__ w2,
                                               const float* __restrict__ watt_s,
                                               const float* __restrict__ watt_d) {
    __shared__ float sw[64 * NC];
    __shared__ float ss[NC], sd[NC];
    int tid = threadIdx.x;
    for (int i = tid; i < 64 * NC; i += blockDim.x) sw[i] = w2[i];
    if (tid < NC) { ss[tid] = watt_s[tid]; sd[tid] = watt_d[tid]; }
    __syncthreads();
    int n = blockIdx.x * blockDim.x + tid;
    if (n >= NN) return;
    float r[64];
    const float4* xr = (const float4*)&g_x1[(size_t)n * 64];
#pragma unroll
    for (int i = 0; i < 16; i++) {
        float4 v = xr[i];
        r[i * 4 + 0] = v.x; r[i * 4 + 1] = v.y; r[i * 4 + 2] = v.z; r[i * 4 + 3] = v.w;
    }
    float as = 0.f, ad = 0.f;
#pragma unroll
    for (int j = 0; j < NC; j++) {
        float sacc = 0.f;
#pragma unroll
        for (int k = 0; k < 64; k++) sacc += r[k] * sw[k * NC + j];
        g_h2[(size_t)n * NCP + j] = sacc;
        as += sacc * ss[j];
        ad += sacc * sd[j];
    }
    g_as2[n] = as;
    g_ad2[n] = ad;
}

// ---------------- edge passes layer 2 (H=1, C=30) ----------------
__global__ void k_esum2(const int* __restrict__ ei, int E, int Etot) {
    int e = blockIdx.x * blockDim.x + threadIdx.x;
    if (e >= Etot) return;
    int s, d; edge_sd(ei, E, e, s, d);
    float v = g_as2[s] + g_ad2[d];
    v = (v > 0.f) ? v : 0.2f * v;
    float ev = __expf(v);
    g_eb2[e] = ev;
    atomicAdd(&g_sum2[d], ev);
}

__global__ void k_emsg2(const int* __restrict__ ei, int E, int Etot,
                        float* __restrict__ a2out) {
    int e = blockIdx.x * blockDim.x + threadIdx.x;
    if (e >= Etot) return;
    int s, d; edge_sd(ei, E, e, s, d);
    float alpha = g_eb2[e] / (g_sum2[d] + 1e-16f);
    a2out[e] = alpha;
    const float4* hp = (const float4*)&g_h2[(size_t)s * NCP];
    float* op = &g_out2[(size_t)d * NCP];
#pragma unroll
    for (int q = 0; q < 7; q++) {
        float4 v = hp[q];
        red_add_v4(op + q * 4, v.x * alpha, v.y * alpha, v.z * alpha, v.w * alpha);
    }
    float2 t = *(const float2*)&g_h2[(size_t)s * NCP + 28];
    red_add_v2(op + 28, t.x * alpha, t.y * alpha);
}

// ---------------- final: elu(out2 + b2), log_softmax ----------------
__global__ void k_final(const float* __restrict__ b2, float* __restrict__ out) {
    int n = blockIdx.x * blockDim.x + threadIdx.x;
    if (n >= NN) return;
    float v[NC];
    float m = -INFINITY;
#pragma unroll
    for (int c = 0; c < NC; c++) {
        float t = g_out2[(size_t)n * NCP + c] + __ldg(&b2[c]);
        t = (t > 0.f) ? t : expm1f(t);
        v[c] = t;
        m = fmaxf(m, t);
    }
    float ssum = 0.f;
#pragma unroll
    for (int c = 0; c < NC; c++) ssum += expf(v[c] - m);
    float lse = m + logf(ssum);
#pragma unroll
    for (int c = 0; c < NC; c++) out[(size_t)n * NC + c] = v[c] - lse;
}

// ---------------- launch ----------------
extern "C" void kernel_launch(void* const* d_in, const int* in_sizes, int n_in,
                              void* d_out, int out_size) {
    const float* x      = (const float*)d_in[0];
    const int*   ei     = (const int*)d_in[1];
    const float* w_res  = (const float*)d_in[2];
    const float* b_res  = (const float*)d_in[3];
    const float* w1     = (const float*)d_in[4];
    const float* att_s1 = (const float*)d_in[5];
    const float* att_d1 = (const float*)d_in[6];
    const float* b1     = (const float*)d_in[7];
    const float* w2     = (const float*)d_in[8];
    const float* att_s2 = (const float*)d_in[9];
    const float* att_d2 = (const float*)d_in[10];
    const float* b2     = (const float*)d_in[11];

    int E = in_sizes[1] / 2;
    int Etot = E + NN;

    float* out = (float*)d_out;
    long long need = (long long)NN * NC + (long long)Etot * HEADS + (long long)Etot;
    float *a1out, *a2out;
    if ((long long)out_size >= need) {
        a1out = out + (size_t)NN * NC;
        a2out = a1out + (size_t)Etot * HEADS;
    } else {
        // alpha outputs not requested: route into scratch (same-slot RMW is safe).
        void* p1 = nullptr; void* p2 = nullptr;
        cudaGetSymbolAddress(&p1, g_eb1);
        cudaGetSymbolAddress(&p2, g_eb2);
        a1out = (float*)p1;
        a2out = (float*)p2;
    }

    k_init_all<<<(NN * D1 + 255) / 256, 256>>>();
    k_gemm1<<<(NN + BM - 1) / BM, 256>>>(x, w1, w_res, b_res);
    k_att1<<<(NN + 127) / 128, 128>>>(att_s1, att_d1);

    k_esum1<<<(Etot + 255) / 256, 256>>>(ei, E, Etot);
    k_emsg1<<<(Etot + 255) / 256, 256>>>(ei, E, Etot, a1out);

    k_x1<<<(NN * D1 / 4 + 255) / 256, 256>>>(b1);
    k_gemm2<<<(NN + 127) / 128, 128>>>(w2, att_s2, att_d2);

    k_esum2<<<(Etot + 255) / 256, 256>>>(ei, E, Etot);
    k_emsg2<<<(Etot + 255) / 256, 256>>>(ei, E, Etot, a2out);

    k_final<<<(NN + 127) / 128, 128>>>(b2, out);
}

// round 8
// speedup vs baseline: 1.3436x; 1.3436x over previous
#include <cuda_runtime.h>
#include <math.h>
#include <stdint.h>

// Problem constants (fixed shapes per reference)
#define NN    50000
#define NF    2000
#define D1    64
#define HEADS 8
#define HID   8
#define NC    30
#define NCP   32          // padded stride for h2/out2 (16B alignment)
#define MAXET 1700000     // >= E(1.6M) + NN(50k)

// ---------------- scratch (device globals; no allocation allowed) ----------
__device__ float g_h1[(size_t)NN * D1];
__device__ float g_res[(size_t)NN * D1];
__device__ float g_as1[NN * HEADS];
__device__ float g_ad1[NN * HEADS];
__device__ float g_sum1[NN * HEADS];
__device__ float g_eb1[(size_t)MAXET * HEADS];
__device__ float g_out1[(size_t)NN * D1];
__device__ float g_x1[(size_t)NN * D1];
__device__ float g_h2[(size_t)NN * NCP];
__device__ float g_as2[NN];
__device__ float g_ad2[NN];
__device__ float g_sum2[NN];
__device__ float g_eb2[MAXET];
__device__ float g_out2[(size_t)NN * NCP];

// ---------------- helpers ----------------
__device__ __forceinline__ void edge_sd(const int* __restrict__ ei, int E, int e,
                                        int& s, int& d) {
    if (e < E) { s = ei[e]; d = ei[E + e]; }
    else       { s = e - E; d = e - E; }   // self loops appended
}
__device__ __forceinline__ void red_add_v4(float* addr, float a, float b, float c, float d) {
    asm volatile("red.global.add.v4.f32 [%0], {%1,%2,%3,%4};"
                 :: "l"(addr), "f"(a), "f"(b), "f"(c), "f"(d) : "memory");
}
__device__ __forceinline__ void red_add_v2(float* addr, float a, float b) {
    asm volatile("red.global.add.v2.f32 [%0], {%1,%2};"
                 :: "l"(addr), "f"(a), "f"(b) : "memory");
}
// packed f32x2: d = a*b + d (two independent fp32 FMAs, .rn — bit-exact fp32)
__device__ __forceinline__ void ffma2(uint64_t& d, uint64_t a, uint64_t b) {
    asm("fma.rn.f32x2 %0, %1, %2, %0;" : "+l"(d) : "l"(a), "l"(b));
}
__device__ __forceinline__ void upk(uint64_t v, float& lo, float& hi) {
    asm("mov.b64 {%0,%1}, %2;" : "=f"(lo), "=f"(hi) : "l"(v));
}

// ---------------- init ----------------
__global__ void k_init_all() {
    int i = blockIdx.x * blockDim.x + threadIdx.x;
    if (i < NN * D1)    g_out1[i] = 0.f;
    if (i < NN * NCP)   g_out2[i] = 0.f;
    if (i < NN * HEADS) g_sum1[i] = 0.f;
    if (i < NN)         g_sum2[i] = 0.f;
}

// ---------------- GEMM1: h1 = x@w1 ; res = x@w_res + b_res ----------------
// M=NN, K=NF, N=128 (cols 0..63 -> h1, 64..127 -> res).
// 128x128 block tile, BK=8, 256 threads, 8x8 per-thread microtile.
// A in shared [k][m] (stride 132, conflict-free): LDS.128 yields row-PAIRS
// directly usable as b64 FMA2 operands (zero movs).
// B in shared DUPLICATED [k][2n],[k][2n+1] (stride 256): LDS.128 yields
// col-SPLAT pairs directly (zero movs).
// Inner loop per k: 6 LDS.128 + 32 FMA2 for 64 FMAs.
#define BM 128
#define BK 8
#define ASTR 132
#define BSTR 256

__global__ __launch_bounds__(256, 2) void k_gemm1(const float* __restrict__ x,
                                                  const float* __restrict__ w1,
                                                  const float* __restrict__ wres,
                                                  const float* __restrict__ bres) {
    __shared__ float As[2][BK][ASTR];    // [buf][k][m]
    __shared__ float Bd[2][BK][BSTR];    // [buf][k][2n] duplicated

    const int tid  = threadIdx.x;
    const int wid  = tid >> 5;
    const int lane = tid & 31;
    const int wm = wid >> 2;            // 0..1
    const int wn = wid & 3;             // 0..3
    const int lm = lane & 7;            // 0..7
    const int ln = lane >> 3;           // 0..3
    const int m0 = wm * 64 + lm * 4;    // rows m0..m0+3 and m0+32..m0+35
    const int n0 = wn * 32 + ln * 4;    // cols n0..n0+3 and n0+16..n0+19
    const int mbase = blockIdx.x * BM;

    // A loader: 128 rows x 8 k = 1024 floats; thread: r=tid>>1, kq=(tid&1)*4
    const int ar  = tid >> 1;            // 0..127
    const int akq = (tid & 1) * 4;       // 0 or 4
    // B loader: 8 k x 128 n; thread: bk=tid>>5 (0..7), bn=(tid&31)*4
    const int bk  = tid >> 5;
    const int bn  = (tid & 31) * 4;

    int arow = mbase + ar; if (arow >= NN) arow = NN - 1;
    const float* bsrc = (bn < 64) ? &w1[bn] : &wres[bn - 64];

    float4 arv, brv;
    arv = *(const float4*)&x[(size_t)arow * NF + akq];
    brv = *(const float4*)&bsrc[(size_t)bk * 64];

    uint64_t acc[4][8];                 // [row-pair][col]
#pragma unroll
    for (int i = 0; i < 4; i++)
#pragma unroll
        for (int j = 0; j < 8; j++) acc[i][j] = 0ull;

    // store tile 0
    {
        float av[4] = {arv.x, arv.y, arv.z, arv.w};
#pragma unroll
        for (int i = 0; i < 4; i++) As[0][akq + i][ar] = av[i];
        *(float4*)&Bd[0][bk][2 * bn]     = make_float4(brv.x, brv.x, brv.y, brv.y);
        *(float4*)&Bd[0][bk][2 * bn + 4] = make_float4(brv.z, brv.z, brv.w, brv.w);
    }
    __syncthreads();

    const int NT = NF / BK;  // 250
    for (int kt = 0; kt < NT; kt++) {
        const int buf = kt & 1;
        if (kt + 1 < NT) {
            const int k0 = (kt + 1) * BK;
            arv = *(const float4*)&x[(size_t)arow * NF + k0 + akq];
            brv = *(const float4*)&bsrc[(size_t)(k0 + bk) * 64];
        }
#pragma unroll
        for (int kk = 0; kk < BK; kk++) {
            // A row-pairs: (m0,m0+1),(m0+2,m0+3),(m0+32,m0+33),(m0+34,m0+35)
            ulonglong2 a01 = *(const ulonglong2*)&As[buf][kk][m0];
            ulonglong2 a23 = *(const ulonglong2*)&As[buf][kk][m0 + 32];
            // B col-splats: cols n0..n0+3 and n0+16..n0+19
            ulonglong2 b01 = *(const ulonglong2*)&Bd[buf][kk][2 * n0];
            ulonglong2 b23 = *(const ulonglong2*)&Bd[buf][kk][2 * n0 + 4];
            ulonglong2 b45 = *(const ulonglong2*)&Bd[buf][kk][2 * n0 + 32];
            ulonglong2 b67 = *(const ulonglong2*)&Bd[buf][kk][2 * n0 + 36];
            uint64_t av[4] = {a01.x, a01.y, a23.x, a23.y};
            uint64_t bv[8] = {b01.x, b01.y, b23.x, b23.y,
                              b45.x, b45.y, b67.x, b67.y};
#pragma unroll
            for (int i = 0; i < 4; i++)
#pragma unroll
                for (int j = 0; j < 8; j++) ffma2(acc[i][j], av[i], bv[j]);
        }
        if (kt + 1 < NT) {
            const int nb = buf ^ 1;
            float av[4] = {arv.x, arv.y, arv.z, arv.w};
#pragma unroll
            for (int i = 0; i < 4; i++) As[nb][akq + i][ar] = av[i];
            *(float4*)&Bd[nb][bk][2 * bn]     = make_float4(brv.x, brv.x, brv.y, brv.y);
            *(float4*)&Bd[nb][bk][2 * bn + 4] = make_float4(brv.z, brv.z, brv.w, brv.w);
            __syncthreads();
        }
    }

    // epilogue: acc[i][j]: i -> row-pairs {m0, m0+2, m0+32, m0+34};
    // j=0..3 -> cols n0..n0+3 ; j=4..7 -> cols n0+16..n0+19
#pragma unroll
    for (int i = 0; i < 4; i++) {
        int rbase = mbase + m0 + ((i < 2) ? (2 * i) : (32 + 2 * (i - 2)));
#pragma unroll
        for (int half = 0; half < 2; half++) {
            int row = rbase + half;
            if (row >= NN) continue;
            float c[8];
#pragma unroll
            for (int j = 0; j < 8; j++) {
                float lo, hi; upk(acc[i][j], lo, hi);
                c[j] = half ? hi : lo;
            }
            float4 vA = make_float4(c[0], c[1], c[2], c[3]);
            float4 vB = make_float4(c[4], c[5], c[6], c[7]);
            if (n0 < 64) {
                *(float4*)&g_h1[(size_t)row * 64 + n0]      = vA;
                *(float4*)&g_h1[(size_t)row * 64 + n0 + 16] = vB;
            } else {
                int nr = n0 - 64;
                vA.x += __ldg(&bres[nr + 0]);  vA.y += __ldg(&bres[nr + 1]);
                vA.z += __ldg(&bres[nr + 2]);  vA.w += __ldg(&bres[nr + 3]);
                vB.x += __ldg(&bres[nr + 16]); vB.y += __ldg(&bres[nr + 17]);
                vB.z += __ldg(&bres[nr + 18]); vB.w += __ldg(&bres[nr + 19]);
                *(float4*)&g_res[(size_t)row * 64 + nr]      = vA;
                *(float4*)&g_res[(size_t)row * 64 + nr + 16] = vB;
            }
        }
    }
}

// ---------------- attention coefficients per node (layer 1) ---------------
__global__ void k_att1(const float* __restrict__ asrc, const float* __restrict__ adst) {
    int n = blockIdx.x * blockDim.x + threadIdx.x;
    if (n >= NN) return;
    const float* hr = &g_h1[(size_t)n * 64];
#pragma unroll
    for (int h = 0; h < HEADS; h++) {
        float s = 0.f, d = 0.f;
#pragma unroll
        for (int c = 0; c < HID; c++) {
            float v = hr[h * HID + c];
            s += v * __ldg(&asrc[h * HID + c]);
            d += v * __ldg(&adst[h * HID + c]);
        }
        g_as1[n * HEADS + h] = s;
        g_ad1[n * HEADS + h] = d;
    }
}

// ---------------- edge passes layer 1 (one thread per edge, 8 heads) -------
__global__ void k_esum1(const int* __restrict__ ei, int E, int Etot) {
    int e = blockIdx.x * blockDim.x + threadIdx.x;
    if (e >= Etot) return;
    int s, d; edge_sd(ei, E, e, s, d);
    float4 s0 = *(const float4*)&g_as1[s * 8];
    float4 s1 = *(const float4*)&g_as1[s * 8 + 4];
    float4 d0 = *(const float4*)&g_ad1[d * 8];
    float4 d1 = *(const float4*)&g_ad1[d * 8 + 4];
    float v[8] = {s0.x + d0.x, s0.y + d0.y, s0.z + d0.z, s0.w + d0.w,
                  s1.x + d1.x, s1.y + d1.y, s1.z + d1.z, s1.w + d1.w};
    float ev[8];
#pragma unroll
    for (int h = 0; h < 8; h++) {
        float t = (v[h] > 0.f) ? v[h] : 0.2f * v[h];
        ev[h] = __expf(t);
    }
    *(float4*)&g_eb1[(size_t)e * 8]     = make_float4(ev[0], ev[1], ev[2], ev[3]);
    *(float4*)&g_eb1[(size_t)e * 8 + 4] = make_float4(ev[4], ev[5], ev[6], ev[7]);
    red_add_v4(&g_sum1[d * 8],     ev[0], ev[1], ev[2], ev[3]);
    red_add_v4(&g_sum1[d * 8 + 4], ev[4], ev[5], ev[6], ev[7]);
}

__global__ void k_emsg1(const int* __restrict__ ei, int E, int Etot,
                        float* __restrict__ a1out) {
    int e = blockIdx.x * blockDim.x + threadIdx.x;
    if (e >= Etot) return;
    int s, d; edge_sd(ei, E, e, s, d);
    float4 e0 = *(const float4*)&g_eb1[(size_t)e * 8];
    float4 e1 = *(const float4*)&g_eb1[(size_t)e * 8 + 4];
    float4 q0 = *(const float4*)&g_sum1[d * 8];
    float4 q1 = *(const float4*)&g_sum1[d * 8 + 4];
    float alpha[8] = {e0.x / (q0.x + 1e-16f), e0.y / (q0.y + 1e-16f),
                      e0.z / (q0.z + 1e-16f), e0.w / (q0.w + 1e-16f),
                      e1.x / (q1.x + 1e-16f), e1.y / (q1.y + 1e-16f),
                      e1.z / (q1.z + 1e-16f), e1.w / (q1.w + 1e-16f)};
    *(float4*)&a1out[(size_t)e * 8]     = make_float4(alpha[0], alpha[1], alpha[2], alpha[3]);
    *(float4*)&a1out[(size_t)e * 8 + 4] = make_float4(alpha[4], alpha[5], alpha[6], alpha[7]);
    const float* hr = &g_h1[(size_t)s * 64];
    float* o = &g_out1[(size_t)d * 64];
#pragma unroll
    for (int h = 0; h < 8; h++) {
        float a = alpha[h];
        float4 h0 = *(const float4*)&hr[h * 8];
        float4 h1v = *(const float4*)&hr[h * 8 + 4];
        red_add_v4(o + h * 8,     h0.x * a, h0.y * a, h0.z * a, h0.w * a);
        red_add_v4(o + h * 8 + 4, h1v.x * a, h1v.y * a, h1v.z * a, h1v.w * a);
    }
}

// ---------------- x1 = elu(out1 + b1 + res), float4 ----------------
__global__ void k_x1(const float* __restrict__ b1) {
    int i4 = blockIdx.x * blockDim.x + threadIdx.x;
    if (i4 >= NN * D1 / 4) return;
    float4 o = *(const float4*)&g_out1[(size_t)i4 * 4];
    float4 r = *(const float4*)&g_res[(size_t)i4 * 4];
    float4 b = *(const float4*)&b1[(i4 & 15) * 4];
    float4 v;
    v.x = o.x + b.x + r.x; v.y = o.y + b.y + r.y;
    v.z = o.z + b.z + r.z; v.w = o.w + b.w + r.w;
    v.x = (v.x > 0.f) ? v.x : expm1f(v.x);
    v.y = (v.y > 0.f) ? v.y : expm1f(v.y);
    v.z = (v.z > 0.f) ? v.z : expm1f(v.z);
    v.w = (v.w > 0.f) ? v.w : expm1f(v.w);
    *(float4*)&g_x1[(size_t)i4 * 4] = v;
}

// ---------------- GEMM2 + attention coefficients (layer 2) ----------------
__global__ __launch_bounds__(128) void k_gemm2(const float* __restrict__ w2,
                                               const float* __restrict__ watt_s,
                                               const float* __restrict__ watt_d) {
    __shared__ float sw[64 * NC];
    __shared__ float ss[NC], sd[NC];
    int tid = threadIdx.x;
    for (int i = tid; i < 64 * NC; i += blockDim.x) sw[i] = w2[i];
    if (tid < NC) { ss[tid] = watt_s[tid]; sd[tid] = watt_d[tid]; }
    __syncthreads();
    int n = blockIdx.x * blockDim.x + tid;
    if (n >= NN) return;
    float r[64];
    const float4* xr = (const float4*)&g_x1[(size_t)n * 64];
#pragma unroll
    for (int i = 0; i < 16; i++) {
        float4 v = xr[i];
        r[i * 4 + 0] = v.x; r[i * 4 + 1] = v.y; r[i * 4 + 2] = v.z; r[i * 4 + 3] = v.w;
    }
    float as = 0.f, ad = 0.f;
#pragma unroll
    for (int j = 0; j < NC; j++) {
        float sacc = 0.f;
#pragma unroll
        for (int k = 0; k < 64; k++) sacc += r[k] * sw[k * NC + j];
        g_h2[(size_t)n * NCP + j] = sacc;
        as += sacc * ss[j];
        ad += sacc * sd[j];
    }
    g_as2[n] = as;
    g_ad2[n] = ad;
}

// ---------------- edge passes layer 2 (H=1, C=30) ----------------
__global__ void k_esum2(const int* __restrict__ ei, int E, int Etot) {
    int e = blockIdx.x * blockDim.x + threadIdx.x;
    if (e >= Etot) return;
    int s, d; edge_sd(ei, E, e, s, d);
    float v = g_as2[s] + g_ad2[d];
    v = (v > 0.f) ? v : 0.2f * v;
    float ev = __expf(v);
    g_eb2[e] = ev;
    atomicAdd(&g_sum2[d], ev);
}

__global__ void k_emsg2(const int* __restrict__ ei, int E, int Etot,
                        float* __restrict__ a2out) {
    int e = blockIdx.x * blockDim.x + threadIdx.x;
    if (e >= Etot) return;
    int s, d; edge_sd(ei, E, e, s, d);
    float alpha = g_eb2[e] / (g_sum2[d] + 1e-16f);
    a2out[e] = alpha;
    const float4* hp = (const float4*)&g_h2[(size_t)s * NCP];
    float* op = &g_out2[(size_t)d * NCP];
#pragma unroll
    for (int q = 0; q < 7; q++) {
        float4 v = hp[q];
        red_add_v4(op + q * 4, v.x * alpha, v.y * alpha, v.z * alpha, v.w * alpha);
    }
    float2 t = *(const float2*)&g_h2[(size_t)s * NCP + 28];
    red_add_v2(op + 28, t.x * alpha, t.y * alpha);
}

// ---------------- final: elu(out2 + b2), log_softmax ----------------
__global__ void k_final(const float* __restrict__ b2, float* __restrict__ out) {
    int n = blockIdx.x * blockDim.x + threadIdx.x;
    if (n >= NN) return;
    float v[NC];
    float m = -INFINITY;
#pragma unroll
    for (int c = 0; c < NC; c++) {
        float t = g_out2[(size_t)n * NCP + c] + __ldg(&b2[c]);
        t = (t > 0.f) ? t : expm1f(t);
        v[c] = t;
        m = fmaxf(m, t);
    }
    float ssum = 0.f;
#pragma unroll
    for (int c = 0; c < NC; c++) ssum += expf(v[c] - m);
    float lse = m + logf(ssum);
#pragma unroll
    for (int c = 0; c < NC; c++) out[(size_t)n * NC + c] = v[c] - lse;
}

// ---------------- launch ----------------
extern "C" void kernel_launch(void* const* d_in, const int* in_sizes, int n_in,
                              void* d_out, int out_size) {
    const float* x      = (const float*)d_in[0];
    const int*   ei     = (const int*)d_in[1];
    const float* w_res  = (const float*)d_in[2];
    const float* b_res  = (const float*)d_in[3];
    const float* w1     = (const float*)d_in[4];
    const float* att_s1 = (const float*)d_in[5];
    const float* att_d1 = (const float*)d_in[6];
    const float* b1     = (const float*)d_in[7];
    const float* w2     = (const float*)d_in[8];
    const float* att_s2 = (const float*)d_in[9];
    const float* att_d2 = (const float*)d_in[10];
    const float* b2     = (const float*)d_in[11];

    int E = in_sizes[1] / 2;
    int Etot = E + NN;

    float* out = (float*)d_out;
    long long need = (long long)NN * NC + (long long)Etot * HEADS + (long long)Etot;
    float *a1out, *a2out;
    if ((long long)out_size >= need) {
        a1out = out + (size_t)NN * NC;
        a2out = a1out + (size_t)Etot * HEADS;
    } else {
        // alpha outputs not requested: route into scratch (same-slot RMW is safe).
        void* p1 = nullptr; void* p2 = nullptr;
        cudaGetSymbolAddress(&p1, g_eb1);
        cudaGetSymbolAddress(&p2, g_eb2);
        a1out = (float*)p1;
        a2out = (float*)p2;
    }

    k_init_all<<<(NN * D1 + 255) / 256, 256>>>();
    k_gemm1<<<(NN + BM - 1) / BM, 256>>>(x, w1, w_res, b_res);
    k_att1<<<(NN + 127) / 128, 128>>>(att_s1, att_d1);

    k_esum1<<<(Etot + 255) / 256, 256>>>(ei, E, Etot);
    k_emsg1<<<(Etot + 255) / 256, 256>>>(ei, E, Etot, a1out);

    k_x1<<<(NN * D1 / 4 + 255) / 256, 256>>>(b1);
    k_gemm2<<<(NN + 127) / 128, 128>>>(w2, att_s2, att_d2);

    k_esum2<<<(Etot + 255) / 256, 256>>>(ei, E, Etot);
    k_emsg2<<<(Etot + 255) / 256, 256>>>(ei, E, Etot, a2out);

    k_final<<<(NN + 127) / 128, 128>>>(b2, out);
}

// round 10
// speedup vs baseline: 1.8861x; 1.4038x over previous
#include <cuda_runtime.h>
#include <cuda_bf16.h>
#include <math.h>
#include <stdint.h>

// Problem constants (fixed shapes per reference)
#define NN    50000
#define NF    2000
#define KPAD  2048
#define D1    64
#define HEADS 8
#define HID   8
#define NC    30
#define NCP   32
#define MAXET 1700000

// ---------------- scratch (device globals; no allocation allowed) ----------
__device__ float g_h1[(size_t)NN * D1];
__device__ float g_res[(size_t)NN * D1];
__device__ float g_as1[NN * HEADS];
__device__ float g_ad1[NN * HEADS];
__device__ float g_sum1[NN * HEADS];
__device__ float g_eb1[(size_t)MAXET * HEADS];
__device__ float g_out1[(size_t)NN * D1];
__device__ float g_x1[(size_t)NN * D1];
__device__ float g_h2[(size_t)NN * NCP];
__device__ float g_as2[NN];
__device__ float g_ad2[NN];
__device__ float g_sum2[NN];
__device__ float g_eb2[MAXET];
__device__ float g_out2[(size_t)NN * NCP];
// pre-transposed + split weights: [n=0..127][k=0..2047] bf16 (zeros past NF)
__device__ unsigned short g_wt_hi[128 * KPAD];
__device__ unsigned short g_wt_lo[128 * KPAD];

// ---------------- helpers ----------------
__device__ __forceinline__ void edge_sd(const int* __restrict__ ei, int E, int e,
                                        int& s, int& d) {
    if (e < E) { s = ei[e]; d = ei[E + e]; }
    else       { s = e - E; d = e - E; }
}
__device__ __forceinline__ void red_add_v4(float* addr, float a, float b, float c, float d) {
    asm volatile("red.global.add.v4.f32 [%0], {%1,%2,%3,%4};"
                 :: "l"(addr), "f"(a), "f"(b), "f"(c), "f"(d) : "memory");
}
__device__ __forceinline__ void red_add_v2(float* addr, float a, float b) {
    asm volatile("red.global.add.v2.f32 [%0], {%1,%2};"
                 :: "l"(addr), "f"(a), "f"(b) : "memory");
}
__device__ __forceinline__ uint32_t smem_u32(const void* p) {
    uint32_t a;
    asm("{ .reg .u64 t; cvta.to.shared.u64 t, %1; cvt.u32.u64 %0, t; }" : "=r"(a) : "l"(p));
    return a;
}
// pack two floats -> bf16x2: first arg to UPPER half, second to LOWER half
__device__ __forceinline__ uint32_t pack_bf16x2(float h, float l) {
    uint32_t r;
    asm("cvt.rn.bf16x2.f32 %0, %1, %2;" : "=r"(r) : "f"(h), "f"(l));
    return r;
}
__device__ __forceinline__ void ldsm4(uint32_t& r0, uint32_t& r1, uint32_t& r2,
                                      uint32_t& r3, uint32_t addr) {
    asm volatile("ldmatrix.sync.aligned.m8n8.x4.shared.b16 {%0,%1,%2,%3}, [%4];"
                 : "=r"(r0), "=r"(r1), "=r"(r2), "=r"(r3) : "r"(addr));
}
__device__ __forceinline__ void mma16816(float* d, uint32_t a0, uint32_t a1,
                                         uint32_t a2, uint32_t a3,
                                         uint32_t b0, uint32_t b1) {
    asm volatile("mma.sync.aligned.m16n8k16.row.col.f32.bf16.bf16.f32 "
                 "{%0,%1,%2,%3}, {%4,%5,%6,%7}, {%8,%9}, {%0,%1,%2,%3};"
                 : "+f"(d[0]), "+f"(d[1]), "+f"(d[2]), "+f"(d[3])
                 : "r"(a0), "r"(a1), "r"(a2), "r"(a3), "r"(b0), "r"(b1));
}
__device__ __forceinline__ void cp16(uint32_t smaddr, const void* gptr) {
    asm volatile("cp.async.cg.shared.global [%0], [%1], 16;"
                 :: "r"(smaddr), "l"(gptr) : "memory");
}
// split fp32 pair -> bf16x2 (hi = truncation, lo = RN residual)
__device__ __forceinline__ void cvt_split(float2 v, uint32_t& hi, uint32_t& lo) {
    uint32_t vx = __float_as_uint(v.x), vy = __float_as_uint(v.y);
    hi = __byte_perm(vx, vy, 0x7632);      // low half = bf16_trunc(v.x), high = v.y
    float hx = __uint_as_float(vx & 0xFFFF0000u);
    float hy = __uint_as_float(vy & 0xFFFF0000u);
    lo = pack_bf16x2(v.y - hy, v.x - hx);
}

// ---------------- init ----------------
__global__ void k_init_all() {
    int i = blockIdx.x * blockDim.x + threadIdx.x;
    if (i < NN * D1)    g_out1[i] = 0.f;
    if (i < NN * NCP)   g_out2[i] = 0.f;
    if (i < NN * HEADS) g_sum1[i] = 0.f;
    if (i < NN)         g_sum2[i] = 0.f;
}

// ---------------- prep: transpose + bf16-split weights -------------------
__global__ void k_prep_w(const float* __restrict__ w1, const float* __restrict__ wres) {
    int idx = blockIdx.x * blockDim.x + threadIdx.x;
    if (idx >= 128 * KPAD) return;
    int n = idx >> 11;
    int k = idx & (KPAD - 1);
    float v = 0.f;
    if (k < NF) v = (n < 64) ? w1[(size_t)k * 64 + n] : wres[(size_t)k * 64 + (n - 64)];
    __nv_bfloat16 hi = __float2bfloat16(v);
    float rem = v - __bfloat162float(hi);
    __nv_bfloat16 lo = __float2bfloat16(rem);
    g_wt_hi[idx] = __bfloat16_as_ushort(hi);
    g_wt_lo[idx] = __bfloat16_as_ushort(lo);
}

// ---------------- GEMM1 via mma.sync bf16x3: [h1 | res] = x @ [w1 | wres] --
// 256 threads = 8 warps; warp w owns rows mbase+w*16 (one m16 fragment row).
// N=128 (cols 0..63 -> h1, 64..127 -> res). BK=32, 63 chunks covers K=2000.
// B smem: [split][buf][n 0..127][64B], 16B-chunk swizzle c ^= (n>>1)&3.
// D = Ahi*Bhi + Ahi*Blo + Alo*Bhi  (bf16x3; rel err ~1e-5)
#define NCH 63

__global__ __launch_bounds__(256, 2) void k_gemm1(const float* __restrict__ x,
                                                  const float* __restrict__ bres) {
    __shared__ __align__(1024) unsigned char Bsm[32768]; // HI:0/8192, LO:16384/24576

    const int tid = threadIdx.x, wid = tid >> 5, lane = tid & 31;
    const int g = lane >> 2, c4 = lane & 3;
    const int mbase = blockIdx.x * 128 + wid * 16;
    int r0 = mbase + g;      if (r0 >= NN) r0 = NN - 1;
    int r1 = mbase + g + 8;  if (r1 >= NN) r1 = NN - 1;
    const uint32_t sb = smem_u32(Bsm);

    // ldmatrix per-lane constants
    const int nL   = (lane & 7) | ((lane & 16) >> 1);  // 0..15
    const int cbit = (lane >> 3) & 1;
    const int q    = cbit ^ ((nL >> 1) & 3);
    const uint32_t lrow = (uint32_t)(nL * 64);

    // cp.async per-thread dest offsets (2 chunks of 16B per split)
    const int fn0 = tid >> 2, fc0 = tid & 3;
    const int fn1 = (tid + 256) >> 2, fc1 = (tid + 256) & 3;
    const uint32_t fd0 = (uint32_t)(fn0 * 64 + ((fc0 ^ ((fn0 >> 1) & 3)) << 4));
    const uint32_t fd1 = (uint32_t)(fn1 * 64 + ((fc1 ^ ((fn1 >> 1) & 3)) << 4));

    float acc[16][4];
#pragma unroll
    for (int i = 0; i < 16; i++)
#pragma unroll
        for (int j = 0; j < 4; j++) acc[i][j] = 0.f;

    // ---- fill chunk 0 ----
    {
        const char* sh0 = (const char*)&g_wt_hi[(size_t)fn0 * KPAD + fc0 * 8];
        const char* sh1 = (const char*)&g_wt_hi[(size_t)fn1 * KPAD + fc1 * 8];
        const char* sl0 = (const char*)&g_wt_lo[(size_t)fn0 * KPAD + fc0 * 8];
        const char* sl1 = (const char*)&g_wt_lo[(size_t)fn1 * KPAD + fc1 * 8];
        cp16(sb + fd0, sh0);             cp16(sb + fd1, sh1);
        cp16(sb + 16384 + fd0, sl0);     cp16(sb + 16384 + fd1, sl1);
        asm volatile("cp.async.commit_group;");
        asm volatile("cp.async.wait_group 0;");
    }
    __syncthreads();

    // A raw prefetch for k16 index 0
    const int kc = 2 * c4;   // 0,2,4,6
    float2 araw[4];
    {
        int col = kc;
        araw[0] = *(const float2*)&x[(size_t)r0 * NF + col];
        araw[1] = *(const float2*)&x[(size_t)r1 * NF + col];
        araw[2] = *(const float2*)&x[(size_t)r0 * NF + col + 8];
        araw[3] = *(const float2*)&x[(size_t)r1 * NF + col + 8];
    }

    for (int c = 0; c < NCH; c++) {
        const uint32_t buf = (uint32_t)(c & 1) * 8192u;
        if (c + 1 < NCH) {
            const uint32_t nbuf = (uint32_t)((c + 1) & 1) * 8192u;
            size_t koff = (size_t)(c + 1) * 32;
            const char* sh0 = (const char*)&g_wt_hi[(size_t)fn0 * KPAD + koff + fc0 * 8];
            const char* sh1 = (const char*)&g_wt_hi[(size_t)fn1 * KPAD + koff + fc1 * 8];
            const char* sl0 = (const char*)&g_wt_lo[(size_t)fn0 * KPAD + koff + fc0 * 8];
            const char* sl1 = (const char*)&g_wt_lo[(size_t)fn1 * KPAD + koff + fc1 * 8];
            cp16(sb + nbuf + fd0, sh0);          cp16(sb + nbuf + fd1, sh1);
            cp16(sb + 16384 + nbuf + fd0, sl0);  cp16(sb + 16384 + nbuf + fd1, sl1);
            asm volatile("cp.async.commit_group;");
        }
#pragma unroll
        for (int s = 0; s < 2; s++) {
            // prefetch next k16 A raw (predicated; even ncol bounds both elems)
            float2 anext[4];
            {
                int ncol = (s == 0) ? (c * 32 + 16 + kc) : ((c + 1) * 32 + kc);
                bool p0 = ncol < NF, p1 = (ncol + 8) < NF;
                anext[0] = p0 ? *(const float2*)&x[(size_t)r0 * NF + ncol] : make_float2(0.f, 0.f);
                anext[1] = p0 ? *(const float2*)&x[(size_t)r1 * NF + ncol] : make_float2(0.f, 0.f);
                anext[2] = p1 ? *(const float2*)&x[(size_t)r0 * NF + ncol + 8] : make_float2(0.f, 0.f);
                anext[3] = p1 ? *(const float2*)&x[(size_t)r1 * NF + ncol + 8] : make_float2(0.f, 0.f);
            }
            // convert current A raw -> hi/lo fragments
            uint32_t ah[4], al[4];
#pragma unroll
            for (int i = 0; i < 4; i++) cvt_split(araw[i], ah[i], al[i]);

            const uint32_t loff = lrow + ((uint32_t)(q ^ (s << 1)) << 4);
#pragma unroll
            for (int nb = 0; nb < 8; nb++) {
                uint32_t addr = sb + buf + (uint32_t)(nb * 1024) + loff;
                uint32_t h0, h1, h2, h3, l0, l1, l2, l3;
                ldsm4(h0, h1, h2, h3, addr);
                ldsm4(l0, l1, l2, l3, addr + 16384u);
                float* d0 = acc[nb * 2];
                float* d1 = acc[nb * 2 + 1];
                mma16816(d0, ah[0], ah[1], ah[2], ah[3], h0, h1);
                mma16816(d0, ah[0], ah[1], ah[2], ah[3], l0, l1);
                mma16816(d0, al[0], al[1], al[2], al[3], h0, h1);
                mma16816(d1, ah[0], ah[1], ah[2], ah[3], h2, h3);
                mma16816(d1, ah[0], ah[1], ah[2], ah[3], l2, l3);
                mma16816(d1, al[0], al[1], al[2], al[3], h2, h3);
            }
#pragma unroll
            for (int i = 0; i < 4; i++) araw[i] = anext[i];
        }
        if (c + 1 < NCH) {
            asm volatile("cp.async.wait_group 0;");
            __syncthreads();
        }
    }

    // ---- epilogue ----
    int row0 = mbase + g, row1 = mbase + g + 8;
#pragma unroll
    for (int nf = 0; nf < 16; nf++) {
        int col = nf * 8 + 2 * c4;
        float2 v0 = make_float2(acc[nf][0], acc[nf][1]);
        float2 v1 = make_float2(acc[nf][2], acc[nf][3]);
        if (col < 64) {
            if (row0 < NN) *(float2*)&g_h1[(size_t)row0 * 64 + col] = v0;
            if (row1 < NN) *(float2*)&g_h1[(size_t)row1 * 64 + col] = v1;
        } else {
            int nr = col - 64;
            float b0 = __ldg(&bres[nr]), b1 = __ldg(&bres[nr + 1]);
            v0.x += b0; v0.y += b1; v1.x += b0; v1.y += b1;
            if (row0 < NN) *(float2*)&g_res[(size_t)row0 * 64 + nr] = v0;
            if (row1 < NN) *(float2*)&g_res[(size_t)row1 * 64 + nr] = v1;
        }
    }
}

// ---------------- attention coefficients per node (layer 1) ---------------
__global__ void k_att1(const float* __restrict__ asrc, const float* __restrict__ adst) {
    int n = blockIdx.x * blockDim.x + threadIdx.x;
    if (n >= NN) return;
    const float* hr = &g_h1[(size_t)n * 64];
#pragma unroll
    for (int h = 0; h < HEADS; h++) {
        float s = 0.f, d = 0.f;
#pragma unroll
        for (int c = 0; c < HID; c++) {
            float v = hr[h * HID + c];
            s += v * __ldg(&asrc[h * HID + c]);
            d += v * __ldg(&adst[h * HID + c]);
        }
        g_as1[n * HEADS + h] = s;
        g_ad1[n * HEADS + h] = d;
    }
}

// ---------------- edge passes layer 1 (one thread per edge, 8 heads) -------
__global__ void k_esum1(const int* __restrict__ ei, int E, int Etot) {
    int e = blockIdx.x * blockDim.x + threadIdx.x;
    if (e >= Etot) return;
    int s, d; edge_sd(ei, E, e, s, d);
    float4 s0 = *(const float4*)&g_as1[s * 8];
    float4 s1 = *(const float4*)&g_as1[s * 8 + 4];
    float4 d0 = *(const float4*)&g_ad1[d * 8];
    float4 d1 = *(const float4*)&g_ad1[d * 8 + 4];
    float v[8] = {s0.x + d0.x, s0.y + d0.y, s0.z + d0.z, s0.w + d0.w,
                  s1.x + d1.x, s1.y + d1.y, s1.z + d1.z, s1.w + d1.w};
    float ev[8];
#pragma unroll
    for (int h = 0; h < 8; h++) {
        float t = (v[h] > 0.f) ? v[h] : 0.2f * v[h];
        ev[h] = __expf(t);
    }
    *(float4*)&g_eb1[(size_t)e * 8]     = make_float4(ev[0], ev[1], ev[2], ev[3]);
    *(float4*)&g_eb1[(size_t)e * 8 + 4] = make_float4(ev[4], ev[5], ev[6], ev[7]);
    red_add_v4(&g_sum1[d * 8],     ev[0], ev[1], ev[2], ev[3]);
    red_add_v4(&g_sum1[d * 8 + 4], ev[4], ev[5], ev[6], ev[7]);
}

__global__ void k_emsg1(const int* __restrict__ ei, int E, int Etot,
                        float* __restrict__ a1out) {
    int e = blockIdx.x * blockDim.x + threadIdx.x;
    if (e >= Etot) return;
    int s, d; edge_sd(ei, E, e, s, d);
    float4 e0 = *(const float4*)&g_eb1[(size_t)e * 8];
    float4 e1 = *(const float4*)&g_eb1[(size_t)e * 8 + 4];
    float4 q0 = *(const float4*)&g_sum1[d * 8];
    float4 q1 = *(const float4*)&g_sum1[d * 8 + 4];
    float alpha[8] = {e0.x / (q0.x + 1e-16f), e0.y / (q0.y + 1e-16f),
                      e0.z / (q0.z + 1e-16f), e0.w / (q0.w + 1e-16f),
                      e1.x / (q1.x + 1e-16f), e1.y / (q1.y + 1e-16f),
                      e1.z / (q1.z + 1e-16f), e1.w / (q1.w + 1e-16f)};
    *(float4*)&a1out[(size_t)e * 8]     = make_float4(alpha[0], alpha[1], alpha[2], alpha[3]);
    *(float4*)&a1out[(size_t)e * 8 + 4] = make_float4(alpha[4], alpha[5], alpha[6], alpha[7]);
    const float* hr = &g_h1[(size_t)s * 64];
    float* o = &g_out1[(size_t)d * 64];
#pragma unroll
    for (int h = 0; h < 8; h++) {
        float a = alpha[h];
        float4 h0 = *(const float4*)&hr[h * 8];
        float4 h1v = *(const float4*)&hr[h * 8 + 4];
        red_add_v4(o + h * 8,     h0.x * a, h0.y * a, h0.z * a, h0.w * a);
        red_add_v4(o + h * 8 + 4, h1v.x * a, h1v.y * a, h1v.z * a, h1v.w * a);
    }
}

// ---------------- x1 = elu(out1 + b1 + res), float4 ----------------
__global__ void k_x1(const float* __restrict__ b1) {
    int i4 = blockIdx.x * blockDim.x + threadIdx.x;
    if (i4 >= NN * D1 / 4) return;
    float4 o = *(const float4*)&g_out1[(size_t)i4 * 4];
    float4 r = *(const float4*)&g_res[(size_t)i4 * 4];
    float4 b = *(const float4*)&b1[(i4 & 15) * 4];
    float4 v;
    v.x = o.x + b.x + r.x; v.y = o.y + b.y + r.y;
    v.z = o.z + b.z + r.z; v.w = o.w + b.w + r.w;
    v.x = (v.x > 0.f) ? v.x : expm1f(v.x);
    v.y = (v.y > 0.f) ? v.y : expm1f(v.y);
    v.z = (v.z > 0.f) ? v.z : expm1f(v.z);
    v.w = (v.w > 0.f) ? v.w : expm1f(v.w);
    *(float4*)&g_x1[(size_t)i4 * 4] = v;
}

// ---------------- GEMM2 + attention coefficients (layer 2) ----------------
__global__ __launch_bounds__(128) void k_gemm2(const float* __restrict__ w2,
                                               const float* __restrict__ watt_s,
                                               const float* __restrict__ watt_d) {
    __shared__ float sw[64 * NC];
    __shared__ float ss[NC], sd[NC];
    int tid = threadIdx.x;
    for (int i = tid; i < 64 * NC; i += blockDim.x) sw[i] = w2[i];
    if (tid < NC) { ss[tid] = watt_s[tid]; sd[tid] = watt_d[tid]; }
    __syncthreads();
    int n = blockIdx.x * blockDim.x + tid;
    if (n >= NN) return;
    float r[64];
    const float4* xr = (const float4*)&g_x1[(size_t)n * 64];
#pragma unroll
    for (int i = 0; i < 16; i++) {
        float4 v = xr[i];
        r[i * 4 + 0] = v.x; r[i * 4 + 1] = v.y; r[i * 4 + 2] = v.z; r[i * 4 + 3] = v.w;
    }
    float as = 0.f, ad = 0.f;
#pragma unroll
    for (int j = 0; j < NC; j++) {
        float sacc = 0.f;
#pragma unroll
        for (int k = 0; k < 64; k++) sacc += r[k] * sw[k * NC + j];
        g_h2[(size_t)n * NCP + j] = sacc;
        as += sacc * ss[j];
        ad += sacc * sd[j];
    }
    g_as2[n] = as;
    g_ad2[n] = ad;
}

// ---------------- edge passes layer 2 (H=1, C=30) ----------------
__global__ void k_esum2(const int* __restrict__ ei, int E, int Etot) {
    int e = blockIdx.x * blockDim.x + threadIdx.x;
    if (e >= Etot) return;
    int s, d; edge_sd(ei, E, e, s, d);
    float v = g_as2[s] + g_ad2[d];
    v = (v > 0.f) ? v : 0.2f * v;
    float ev = __expf(v);
    g_eb2[e] = ev;
    atomicAdd(&g_sum2[d], ev);
}

__global__ void k_emsg2(const int* __restrict__ ei, int E, int Etot,
                        float* __restrict__ a2out) {
    int e = blockIdx.x * blockDim.x + threadIdx.x;
    if (e >= Etot) return;
    int s, d; edge_sd(ei, E, e, s, d);
    float alpha = g_eb2[e] / (g_sum2[d] + 1e-16f);
    a2out[e] = alpha;
    const float4* hp = (const float4*)&g_h2[(size_t)s * NCP];
    float* op = &g_out2[(size_t)d * NCP];
#pragma unroll
    for (int q = 0; q < 7; q++) {
        float4 v = hp[q];
        red_add_v4(op + q * 4, v.x * alpha, v.y * alpha, v.z * alpha, v.w * alpha);
    }
    float2 t = *(const float2*)&g_h2[(size_t)s * NCP + 28];
    red_add_v2(op + 28, t.x * alpha, t.y * alpha);
}

// ---------------- final: elu(out2 + b2), log_softmax ----------------
__global__ void k_final(const float* __restrict__ b2, float* __restrict__ out) {
    int n = blockIdx.x * blockDim.x + threadIdx.x;
    if (n >= NN) return;
    float v[NC];
    float m = -INFINITY;
#pragma unroll
    for (int c = 0; c < NC; c++) {
        float t = g_out2[(size_t)n * NCP + c] + __ldg(&b2[c]);
        t = (t > 0.f) ? t : expm1f(t);
        v[c] = t;
        m = fmaxf(m, t);
    }
    float ssum = 0.f;
#pragma unroll
    for (int c = 0; c < NC; c++) ssum += expf(v[c] - m);
    float lse = m + logf(ssum);
#pragma unroll
    for (int c = 0; c < NC; c++) out[(size_t)n * NC + c] = v[c] - lse;
}

// ---------------- launch ----------------
extern "C" void kernel_launch(void* const* d_in, const int* in_sizes, int n_in,
                              void* d_out, int out_size) {
    const float* x      = (const float*)d_in[0];
    const int*   ei     = (const int*)d_in[1];
    const float* w_res  = (const float*)d_in[2];
    const float* b_res  = (const float*)d_in[3];
    const float* w1     = (const float*)d_in[4];
    const float* att_s1 = (const float*)d_in[5];
    const float* att_d1 = (const float*)d_in[6];
    const float* b1     = (const float*)d_in[7];
    const float* w2     = (const float*)d_in[8];
    const float* att_s2 = (const float*)d_in[9];
    const float* att_d2 = (const float*)d_in[10];
    const float* b2     = (const float*)d_in[11];

    int E = in_sizes[1] / 2;
    int Etot = E + NN;

    float* out = (float*)d_out;
    long long need = (long long)NN * NC + (long long)Etot * HEADS + (long long)Etot;
    float *a1out, *a2out;
    if ((long long)out_size >= need) {
        a1out = out + (size_t)NN * NC;
        a2out = a1out + (size_t)Etot * HEADS;
    } else {
        void* p1 = nullptr; void* p2 = nullptr;
        cudaGetSymbolAddress(&p1, g_eb1);
        cudaGetSymbolAddress(&p2, g_eb2);
        a1out = (float*)p1;
        a2out = (float*)p2;
    }

    k_init_all<<<(NN * D1 + 255) / 256, 256>>>();
    k_prep_w<<<(128 * KPAD + 255) / 256, 256>>>(w1, w_res);
    k_gemm1<<<(NN + 127) / 128, 256>>>(x, b_res);
    k_att1<<<(NN + 127) / 128, 128>>>(att_s1, att_d1);

    k_esum1<<<(Etot + 255) / 256, 256>>>(ei, E, Etot);
    k_emsg1<<<(Etot + 255) / 256, 256>>>(ei, E, Etot, a1out);

    k_x1<<<(NN * D1 / 4 + 255) / 256, 256>>>(b1);
    k_gemm2<<<(NN + 127) / 128, 128>>>(w2, att_s2, att_d2);

    k_esum2<<<(Etot + 255) / 256, 256>>>(ei, E, Etot);
    k_emsg2<<<(Etot + 255) / 256, 256>>>(ei, E, Etot, a2out);

    k_final<<<(NN + 127) / 128, 128>>>(b2, out);
}